// round 16
// baseline (speedup 1.0000x reference)
#include <cuda_runtime.h>
#include <stdint.h>

#define P1 2654435761u
#define P2 805459861u
#define NBINS (1 << 18)     // 2^18 morton bins (6 bits/axis, 4^3-voxel bins)
#define NCHUNK (NBINS / 256)  // 1024 chunks of 256 bins
#define CAP   2100000       // max points for the sort path

__device__ float4 g_sorted[CAP];     // xyz + original index (bits) per point
__device__ int g_hist[NBINS];
__device__ int g_base[NBINS];        // exclusive scan within 256-bin chunk
__device__ int g_cnt[NBINS];
__device__ int g_chunksum[NCHUNK];
__device__ int g_chunkoff[NCHUNK];   // global exclusive offset per chunk
__device__ int g_supersum[4];        // sums of 256-chunk groups

// ---------- helpers ----------
__device__ __forceinline__ float ldg_stream(const float* p) {
    float v;
    asm volatile("ld.global.cs.f32 %0, [%1];" : "=f"(v) : "l"(p));
    return v;
}
__device__ __forceinline__ void stg_stream(float4* p, float4 v) {
    asm volatile("st.global.cs.v4.f32 [%0], {%1,%2,%3,%4};"
                 :: "l"(p), "f"(v.x), "f"(v.y), "f"(v.z), "f"(v.w) : "memory");
}
__device__ __forceinline__ unsigned expand3(unsigned x) {
    x &= 0x3FFu;
    x = (x | (x << 16)) & 0x030000FFu;
    x = (x | (x << 8))  & 0x0300F00Fu;
    x = (x | (x << 4))  & 0x030C30C3u;
    x = (x | (x << 2))  & 0x09249249u;
    return x;
}
__device__ __forceinline__ unsigned bin_key(float px, float py, float pz) {
    const int bx = (int)floorf(px / 0.005f);
    const int by = (int)floorf(py / 0.005f);
    const int bz = (int)floorf(pz / 0.005f);
    const unsigned kx = ((unsigned)bx >> 2) & 63u;
    const unsigned ky = ((unsigned)by >> 2) & 63u;
    const unsigned kz = ((unsigned)bz >> 2) & 63u;
    return expand3(kx) | (expand3(ky) << 1) | (expand3(kz) << 2);
}

// ---------- sort prepass (all blocks are 256 threads) ----------
__global__ void k_zero() {
    int i = blockIdx.x * blockDim.x + threadIdx.x;
    if (i < NBINS) { g_hist[i] = 0; g_cnt[i] = 0; }
}

__global__ void k_hist(const float* __restrict__ pts, int n) {
    int i = blockIdx.x * blockDim.x + threadIdx.x;
    if (i >= n) return;
    atomicAdd(&g_hist[bin_key(pts[3 * (size_t)i + 0],
                              pts[3 * (size_t)i + 1],
                              pts[3 * (size_t)i + 2])], 1);
}

__device__ __forceinline__ int scan256(int v, int t, int* s) {
    s[t] = v;
    __syncthreads();
#pragma unroll
    for (int off = 1; off < 256; off <<= 1) {
        int add = (t >= off) ? s[t - off] : 0;
        __syncthreads();
        s[t] += add;
        __syncthreads();
    }
    return s[t];           // inclusive
}

// level 1: 1024 blocks x 256 threads — scan each 256-bin chunk.
__global__ void k_scan_l1() {
    __shared__ int s[256];
    const int t = threadIdx.x;
    const int i = blockIdx.x * 256 + t;
    const int v = g_hist[i];
    const int inc = scan256(v, t, s);
    g_base[i] = inc - v;
    if (t == 255) g_chunksum[blockIdx.x] = inc;
}

// level 2: 4 blocks x 256 threads — scan chunk sums within each 256-chunk group.
__global__ void k_scan_l2() {
    __shared__ int s[256];
    const int t = threadIdx.x;
    const int i = blockIdx.x * 256 + t;
    const int v = g_chunksum[i];
    const int inc = scan256(v, t, s);
    g_chunkoff[i] = inc - v;      // offset within group, fixed up in l3
    if (t == 255) g_supersum[blockIdx.x] = inc;
}

// level 3: 1 block x 256 threads — add group offsets to chunk offsets.
__global__ void k_scan_l3() {
    const int t = threadIdx.x;
    // exclusive scan of the 4 supersums (tiny, compute in every thread)
    int off0 = 0;
    int off1 = g_supersum[0];
    int off2 = off1 + g_supersum[1];
    int off3 = off2 + g_supersum[2];
    const int goff[4] = {off0, off1, off2, off3};
#pragma unroll
    for (int g = 0; g < 4; g++) {
        g_chunkoff[g * 256 + t] += goff[g];
    }
}

__global__ void k_scatter(const float* __restrict__ pts, int n) {
    int i = blockIdx.x * blockDim.x + threadIdx.x;
    if (i >= n) return;
    const float px = pts[3 * (size_t)i + 0];
    const float py = pts[3 * (size_t)i + 1];
    const float pz = pts[3 * (size_t)i + 2];
    const unsigned key = bin_key(px, py, pz);
    const int pos = g_base[key] + g_chunkoff[key >> 8] + atomicAdd(&g_cnt[key], 1);
    g_sorted[pos] = make_float4(px, py, pz, __int_as_float(i));
}

// ---------- main gather kernel (pair-lane, measured-best microstructure) ----------
template <bool POW2, bool SORTED>
__global__ __launch_bounds__(256)
void k_interp(const float* __restrict__ pts,
              const float* __restrict__ feat,
              float* __restrict__ out,
              int n, unsigned buckets, unsigned mask)
{
    const unsigned lane = threadIdx.x & 31u;
    const int gwarp = (int)((blockIdx.x * blockDim.x + threadIdx.x) >> 5);

    const int p_raw = gwarp * 16 + (int)(lane >> 1);   // 16 points per warp
    const bool valid = (p_raw < n);
    const int p = valid ? p_raw : 0;
    const unsigned h = lane & 1u;

    float px, py, pz;
    int oidx;
    if (SORTED) {
        const float4 sp = g_sorted[p];                 // pair-lanes broadcast
        px = sp.x; py = sp.y; pz = sp.z;
        oidx = __float_as_int(sp.w);
    } else {
        px = ldg_stream(pts + 3 * (size_t)p + 0);
        py = ldg_stream(pts + 3 * (size_t)p + 1);
        pz = ldg_stream(pts + 3 * (size_t)p + 2);
        oidx = p_raw;
    }

    const float qx = px / 0.005f;
    const float qy = py / 0.005f;
    const float qz = pz / 0.005f;

    const float bxf = floorf(qx);
    const float byf = floorf(qy);
    const float bzf = floorf(qz);
    const int bx = (int)bxf, by = (int)byf, bz = (int)bzf;

    const float fx = qx - bxf;
    const float fy = qy - byf;
    const float fz = qz - bzf;

    const unsigned hx0 = (unsigned)bx;
    const unsigned hx1 = (unsigned)(bx + 1);
    const unsigned hy0 = (unsigned)by * P1;
    const unsigned hy1 = hy0 + P1;
    const unsigned hz0 = (unsigned)bz * P2;
    const unsigned hz1 = hz0 + P2;

    unsigned slot[8];
    {
        const unsigned s0 = hx0 ^ hy0 ^ hz0;
        const unsigned s1 = hx1 ^ hy0 ^ hz0;
        const unsigned s2 = hx0 ^ hy1 ^ hz0;
        const unsigned s3 = hx1 ^ hy1 ^ hz0;
        const unsigned s4 = hx0 ^ hy0 ^ hz1;
        const unsigned s5 = hx1 ^ hy0 ^ hz1;
        const unsigned s6 = hx0 ^ hy1 ^ hz1;
        const unsigned s7 = hx1 ^ hy1 ^ hz1;
        if (POW2) {
            slot[0] = s0 & mask; slot[1] = s1 & mask; slot[2] = s2 & mask; slot[3] = s3 & mask;
            slot[4] = s4 & mask; slot[5] = s5 & mask; slot[6] = s6 & mask; slot[7] = s7 & mask;
        } else {
            slot[0] = s0 % buckets; slot[1] = s1 % buckets; slot[2] = s2 % buckets; slot[3] = s3 % buckets;
            slot[4] = s4 % buckets; slot[5] = s5 % buckets; slot[6] = s6 % buckets; slot[7] = s7 % buckets;
        }
    }

    const float4* fbase = reinterpret_cast<const float4*>(feat);
    float4 v[8];
#pragma unroll
    for (int c = 0; c < 8; c++) {
        v[c] = __ldg(fbase + ((size_t)slot[c] * 2 + h));
    }

    const float wx0 = 1.0f - fx, wx1 = fx;
    const float wy0 = 1.0f - fy, wy1 = fy;
    const float wz0 = 1.0f - fz, wz1 = fz;
    float w[8];
    w[0] = wx0 * wy0 * wz0;
    w[1] = wx1 * wy0 * wz0;
    w[2] = wx0 * wy1 * wz0;
    w[3] = wx1 * wy1 * wz0;
    w[4] = wx0 * wy0 * wz1;
    w[5] = wx1 * wy0 * wz1;
    w[6] = wx0 * wy1 * wz1;
    w[7] = wx1 * wy1 * wz1;

    float a0 = 0.f, a1 = 0.f, a2 = 0.f, a3 = 0.f;
#pragma unroll
    for (int c = 0; c < 8; c++) {
        const float wc = w[c];
        a0 = fmaf(wc, v[c].x, a0);
        a1 = fmaf(wc, v[c].y, a1);
        a2 = fmaf(wc, v[c].z, a2);
        a3 = fmaf(wc, v[c].w, a3);
    }

    if (valid) {
        stg_stream(reinterpret_cast<float4*>(out) + ((size_t)oidx * 2 + h),
                   make_float4(a0, a1, a2, a3));
    }
}

extern "C" void kernel_launch(void* const* d_in, const int* in_sizes, int n_in,
                              void* d_out, int out_size)
{
    const float* pts  = (const float*)d_in[0];
    const float* feat = (const float*)d_in[1];
    float* out = (float*)d_out;

    int n = in_sizes[0] / 3;
    unsigned buckets = (unsigned)(in_sizes[1] / 8);
    unsigned mask = buckets - 1u;
    bool pow2 = (buckets & (buckets - 1u)) == 0u;

    const int T = 256;
    const int blocks_n = (n + T - 1) / T;
    long long warps = ((long long)n + 15) / 16;
    const int blocks_main = (int)((warps * 32 + T - 1) / T);

    if (n <= CAP) {
        k_zero<<<(NBINS + T - 1) / T, T>>>();
        k_hist<<<blocks_n, T>>>(pts, n);
        k_scan_l1<<<NCHUNK, T>>>();
        k_scan_l2<<<4, T>>>();
        k_scan_l3<<<1, T>>>();
        k_scatter<<<blocks_n, T>>>(pts, n);
        if (pow2) k_interp<true,  true><<<blocks_main, T>>>(pts, feat, out, n, buckets, mask);
        else      k_interp<false, true><<<blocks_main, T>>>(pts, feat, out, n, buckets, mask);
    } else {
        if (pow2) k_interp<true,  false><<<blocks_main, T>>>(pts, feat, out, n, buckets, mask);
        else      k_interp<false, false><<<blocks_main, T>>>(pts, feat, out, n, buckets, mask);
    }
}

// round 17
// speedup vs baseline: 1.6743x; 1.6743x over previous
#include <cuda_runtime.h>
#include <stdint.h>

#define P1 2654435761u
#define P2 805459861u

// Table gather with 128B line-granular L2 fill (measured win in R11).
__device__ __forceinline__ float4 ldg_tab128(const float4* p) {
    float4 v;
    asm volatile("ld.global.nc.L2::128B.v4.f32 {%0,%1,%2,%3}, [%4];"
                 : "=f"(v.x), "=f"(v.y), "=f"(v.z), "=f"(v.w) : "l"(p));
    return v;
}

// Streaming (evict-first) accessors for pts/out.
__device__ __forceinline__ float ldg_stream(const float* p) {
    float v;
    asm volatile("ld.global.cs.f32 %0, [%1];" : "=f"(v) : "l"(p));
    return v;
}
__device__ __forceinline__ void stg_stream(float4* p, float4 v) {
    asm volatile("st.global.cs.v4.f32 [%0], {%1,%2,%3,%4};"
                 :: "l"(p), "f"(v.x), "f"(v.y), "f"(v.z), "f"(v.w) : "memory");
}

// Measured-best layout (R11, 88.1us): 2 lanes per point, lane 2k+h handles
// point k, 16B half h of the 32B feature row; pair-lanes share each 128B line
// per gather -> 8 L1tex wavefronts/point, no cross-lane reduction.
// NEW vs R11: __launch_bounds__(256, 8) -> <=32 regs -> 8 blocks/SM (2048
// threads, +14% resident warps) to raise in-flight misses in this
// latency-exposed kernel.
template <bool POW2>
__global__ __launch_bounds__(256, 8)
void hash_interp_half(const float* __restrict__ pts,
                      const float* __restrict__ feat,
                      float* __restrict__ out,
                      int n, unsigned buckets, unsigned mask)
{
    const unsigned lane = threadIdx.x & 31u;
    const int gwarp = (int)((blockIdx.x * blockDim.x + threadIdx.x) >> 5);

    const int p_raw = gwarp * 16 + (int)(lane >> 1);   // 16 points per warp
    const bool valid = (p_raw < n);
    const int p = valid ? p_raw : 0;
    const unsigned h = lane & 1u;                      // 16B half of the row

    // point coords (pair-lanes read identical addresses -> broadcast)
    const float px = ldg_stream(pts + 3 * (size_t)p + 0);
    const float py = ldg_stream(pts + 3 * (size_t)p + 1);
    const float pz = ldg_stream(pts + 3 * (size_t)p + 2);

    // continuous grid coords, matching reference's pts / 0.005
    const float qx = px / 0.005f;
    const float qy = py / 0.005f;
    const float qz = pz / 0.005f;

    const float bxf = floorf(qx);
    const float byf = floorf(qy);
    const float bzf = floorf(qz);
    const int bx = (int)bxf, by = (int)byf, bz = (int)bzf;

    const float fx = qx - bxf;
    const float fy = qy - byf;
    const float fz = qz - bzf;

    // per-axis hash terms
    const unsigned hx0 = (unsigned)bx;           // * 1
    const unsigned hx1 = (unsigned)(bx + 1);
    const unsigned hy0 = (unsigned)by * P1;
    const unsigned hy1 = hy0 + P1;
    const unsigned hz0 = (unsigned)bz * P2;
    const unsigned hz1 = hz0 + P2;

    unsigned slot[8];
    {
        const unsigned s0 = hx0 ^ hy0 ^ hz0;
        const unsigned s1 = hx1 ^ hy0 ^ hz0;
        const unsigned s2 = hx0 ^ hy1 ^ hz0;
        const unsigned s3 = hx1 ^ hy1 ^ hz0;
        const unsigned s4 = hx0 ^ hy0 ^ hz1;
        const unsigned s5 = hx1 ^ hy0 ^ hz1;
        const unsigned s6 = hx0 ^ hy1 ^ hz1;
        const unsigned s7 = hx1 ^ hy1 ^ hz1;
        if (POW2) {
            slot[0] = s0 & mask; slot[1] = s1 & mask; slot[2] = s2 & mask; slot[3] = s3 & mask;
            slot[4] = s4 & mask; slot[5] = s5 & mask; slot[6] = s6 & mask; slot[7] = s7 & mask;
        } else {
            slot[0] = s0 % buckets; slot[1] = s1 % buckets; slot[2] = s2 % buckets; slot[3] = s3 % buckets;
            slot[4] = s4 % buckets; slot[5] = s5 % buckets; slot[6] = s6 % buckets; slot[7] = s7 % buckets;
        }
    }

    // issue all 8 gathers up-front for MLP; pair-lanes share each 128B line
    const float4* fbase = reinterpret_cast<const float4*>(feat);
    float4 v[8];
#pragma unroll
    for (int c = 0; c < 8; c++) {
        v[c] = ldg_tab128(fbase + ((size_t)slot[c] * 2 + h));
    }

    // trilinear weights (same multiply order as reference); after the loads so
    // the ALU overlaps memory latency.
    const float wx0 = 1.0f - fx, wx1 = fx;
    const float wy0 = 1.0f - fy, wy1 = fy;
    const float wz0 = 1.0f - fz, wz1 = fz;
    float w[8];
    w[0] = wx0 * wy0 * wz0;
    w[1] = wx1 * wy0 * wz0;
    w[2] = wx0 * wy1 * wz0;
    w[3] = wx1 * wy1 * wz0;
    w[4] = wx0 * wy0 * wz1;
    w[5] = wx1 * wy0 * wz1;
    w[6] = wx0 * wy1 * wz1;
    w[7] = wx1 * wy1 * wz1;

    float a0 = 0.f, a1 = 0.f, a2 = 0.f, a3 = 0.f;
#pragma unroll
    for (int c = 0; c < 8; c++) {
        const float wc = w[c];
        a0 = fmaf(wc, v[c].x, a0);
        a1 = fmaf(wc, v[c].y, a1);
        a2 = fmaf(wc, v[c].z, a2);
        a3 = fmaf(wc, v[c].w, a3);
    }

    if (valid) {
        // lane 2k -> float4 index 2p, lane 2k+1 -> 2p+1: fully coalesced
        stg_stream(reinterpret_cast<float4*>(out) + ((size_t)p_raw * 2 + h),
                   make_float4(a0, a1, a2, a3));
    }
}

extern "C" void kernel_launch(void* const* d_in, const int* in_sizes, int n_in,
                              void* d_out, int out_size)
{
    const float* pts  = (const float*)d_in[0];
    const float* feat = (const float*)d_in[1];
    float* out = (float*)d_out;

    int n = in_sizes[0] / 3;
    unsigned buckets = (unsigned)(in_sizes[1] / 8);
    unsigned mask = buckets - 1u;
    bool pow2 = (buckets & (buckets - 1u)) == 0u;

    // 2 lanes per point -> 16 points per warp
    long long warps = ((long long)n + 15) / 16;
    long long threads_total = warps * 32;
    int threads = 256;
    int blocks = (int)((threads_total + threads - 1) / threads);

    if (pow2) {
        hash_interp_half<true><<<blocks, threads>>>(pts, feat, out, n, buckets, mask);
    } else {
        hash_interp_half<false><<<blocks, threads>>>(pts, feat, out, n, buckets, mask);
    }
}